// round 9
// baseline (speedup 1.0000x reference)
#include <cuda_runtime.h>
#include <math.h>

#define T_STEPS 64
#define BATCH   512
#define NIMG    (T_STEPS*BATCH)   // 32768
#define HID     112
#define G4      448               // 4*HID
#define NB      (BATCH*10)        // 5120 LSTM rows
#define LSTM_THREADS 336          // 112 j x 3 row-groups
#define LROWS   36
#define LSTM_BLOCKS 143

typedef unsigned long long ull;

// ---- f32x2 helpers ----
__device__ __forceinline__ ull pack2(float lo, float hi) {
    ull r;
    asm("mov.b64 %0, {%1, %2};" : "=l"(r) : "r"(__float_as_uint(lo)), "r"(__float_as_uint(hi)));
    return r;
}
__device__ __forceinline__ ull dup2(float v) { return pack2(v, v); }
__device__ __forceinline__ void fma2(ull& d, ull a, ull b) {
    asm("fma.rn.f32x2 %0, %1, %2, %0;" : "+l"(d) : "l"(a), "l"(b));
}
__device__ __forceinline__ void unpack2(ull v, float& lo, float& hi) {
    unsigned ulo, uhi;
    asm("mov.b64 {%0, %1}, %2;" : "=r"(ulo), "=r"(uhi) : "l"(v));
    lo = __uint_as_float(ulo); hi = __uint_as_float(uhi);
}

__device__ __forceinline__ float fsig(float x) {
    return __fdividef(1.f, 1.f + __expf(-x));
}
__device__ __forceinline__ float ftanh(float x) {
    float e = __expf(2.f * x);
    return 1.f - __fdividef(2.f, e + 1.f);
}

// ---- scratch ----
__device__ float g_feat1[(size_t)NIMG * 10 * 144];
__device__ float g_feat2[(size_t)NIMG * 20 * 36];
__device__ float g_x   [(size_t)NIMG * 360];
// g_gx layout: [row][jj*4 + gate]
__device__ float g_gx  [(size_t)T_STEPS * NB * G4];
__device__ float g_whhT[HID * G4];

// ---------------------------------------------------------------------------
__global__ void k_transpose(const float* __restrict__ whh) {
    int idx = blockIdx.x * 256 + threadIdx.x;
    if (idx < HID * G4) {
        int k = idx / G4, col = idx % G4;
        g_whhT[idx] = whh[col * HID + k];
    }
}

// ---------------------------------------------------------------------------
// conv1: (N,1,24,24) -> relu -> pool2 -> (N,10,12,12). 16 images/block.
// ---------------------------------------------------------------------------
__global__ void __launch_bounds__(256, 2)
k_conv1(const float* __restrict__ imgs,
        const float* __restrict__ w1, const float* __restrict__ b1) {
    __shared__ __align__(16) float sin_[16 * 576];
    __shared__ float sw[90];
    __shared__ float sb[10];
    int tid = threadIdx.x;
    size_t img0 = (size_t)blockIdx.x * 16;
    {
        const float4* src = (const float4*)(imgs + img0 * 576);
        float4* dst = (float4*)sin_;
        #pragma unroll
        for (int k = 0; k < 9; k++) dst[tid + k * 256] = src[tid + k * 256];
    }
    if (tid < 90) sw[tid] = w1[tid];
    if (tid < 10) sb[tid] = b1[tid];
    __syncthreads();

    #pragma unroll 1
    for (int k = 0; k < 9; k++) {
        int it = tid + k * 256;
        int ii = it / 144, p = it % 144;
        int ph = p / 12, pw = p % 12;
        int y0 = 2 * ph - 1, x0 = 2 * pw - 1;
        float patch[4][4];
        #pragma unroll
        for (int dy = 0; dy < 4; dy++) {
            int y = y0 + dy;
            #pragma unroll
            for (int dx = 0; dx < 4; dx++) {
                int x = x0 + dx;
                patch[dy][dx] = (y >= 0 && y < 24 && x >= 0 && x < 24)
                                ? sin_[ii * 576 + y * 24 + x] : 0.f;
            }
        }
        ull pp[4][3];
        #pragma unroll
        for (int r = 0; r < 4; r++)
            #pragma unroll
            for (int dx = 0; dx < 3; dx++)
                pp[r][dx] = pack2(patch[r][dx], patch[r][dx + 1]);

        size_t obase = (img0 + ii) * 1440;
        #pragma unroll 1
        for (int oc = 0; oc < 10; oc++) {
            float w[9];
            #pragma unroll
            for (int q = 0; q < 9; q++) w[q] = sw[oc * 9 + q];
            float bb = sb[oc];
            ull acc0 = dup2(bb), acc1 = dup2(bb);
            #pragma unroll
            for (int dy = 0; dy < 3; dy++)
                #pragma unroll
                for (int dx = 0; dx < 3; dx++) {
                    ull wd = dup2(w[dy * 3 + dx]);
                    fma2(acc0, pp[dy][dx], wd);
                    fma2(acc1, pp[dy + 1][dx], wd);
                }
            float v00, v01, v10, v11;
            unpack2(acc0, v00, v01); unpack2(acc1, v10, v11);
            float mx = fmaxf(fmaxf(v00, v01), fmaxf(v10, v11));
            g_feat1[obase + oc * 144 + p] = fmaxf(mx, 0.f);
        }
    }
}

// ---------------------------------------------------------------------------
// conv2: (N,10,12,12) -> relu -> pool2 -> (N,20,6,6). 2 images / block.
// SMEM holds pre-packed overlapping input pairs + pre-dup'd weights:
// inner loop has ZERO pack/dup movs.
// ---------------------------------------------------------------------------
__global__ void __launch_bounds__(256, 1)
k_conv2(const float* __restrict__ w2, const float* __restrict__ b2) {
    __shared__ __align__(16) ull spk2[2 * 10 * 12 * 13];  // 3120 ull = 24960 B
    __shared__ __align__(16) ull swd2[20 * 10 * 10];      // 2000 ull = 16000 B
    __shared__ float sb[20];
    int tid = threadIdx.x;
    size_t img0 = (size_t)blockIdx.x * 2;

    // weights: dup'd, padded groups of 10
    for (int i = tid; i < 1800; i += 256) {
        int g = i / 9, q = i % 9;
        swd2[g * 10 + q] = dup2(w2[i]);
    }
    // inputs: overlapping pairs over cols -1..11 -> 13 packs per row
    for (int r = tid; r < 240; r += 256) {
        int ii = r / 120, rest = r % 120;
        int ic = rest / 12, y = rest % 12;
        const float4* sp = (const float4*)(g_feat1 + (img0 + ii) * 1440 + ic * 144 + y * 12);
        float4 a = sp[0], b = sp[1], c = sp[2];
        ull* dst = spk2 + r * 13;
        dst[0]  = pack2(0.f, a.x);
        dst[1]  = pack2(a.x, a.y);
        dst[2]  = pack2(a.y, a.z);
        dst[3]  = pack2(a.z, a.w);
        dst[4]  = pack2(a.w, b.x);
        dst[5]  = pack2(b.x, b.y);
        dst[6]  = pack2(b.y, b.z);
        dst[7]  = pack2(b.z, b.w);
        dst[8]  = pack2(b.w, c.x);
        dst[9]  = pack2(c.x, c.y);
        dst[10] = pack2(c.y, c.z);
        dst[11] = pack2(c.z, c.w);
        dst[12] = pack2(c.w, 0.f);
    }
    if (tid < 20) sb[tid] = b2[tid];
    __syncthreads();

    if (tid >= 240) return;
    int ii   = tid / 120;
    int rem  = tid % 120;
    int og   = rem / 12;
    int rr   = rem % 12;
    int ph   = rr / 2;
    int half = rr % 2;

    ull acc[2][3][2];
    #pragma unroll
    for (int o = 0; o < 2; o++) {
        ull bb = dup2(sb[2 * og + o]);
        #pragma unroll
        for (int pw = 0; pw < 3; pw++) { acc[o][pw][0] = bb; acc[o][pw][1] = bb; }
    }

    #pragma unroll 1
    for (int ic = 0; ic < 10; ic++) {
        ull wd[2][9];
        #pragma unroll
        for (int o = 0; o < 2; o++) {
            const ull* wp = swd2 + ((2 * og + o) * 10 + ic) * 10;
            const ulonglong2* wp2 = (const ulonglong2*)wp;
            ulonglong2 w01 = wp2[0], w23 = wp2[1], w45 = wp2[2], w67 = wp2[3];
            wd[o][0] = w01.x; wd[o][1] = w01.y; wd[o][2] = w23.x; wd[o][3] = w23.y;
            wd[o][4] = w45.x; wd[o][5] = w45.y; wd[o][6] = w67.x; wd[o][7] = w67.y;
            wd[o][8] = wp[8];
        }
        const ull* rb = spk2 + (ii * 10 + ic) * 156;   // 12 rows * 13
        #pragma unroll
        for (int dy = 0; dy < 4; dy++) {
            int y = 2 * ph - 1 + dy;
            ull v[7];
            if (y >= 0 && y < 12) {
                const ull* rp = rb + y * 13 + 6 * half;
                #pragma unroll
                for (int cc = 0; cc < 7; cc++) v[cc] = rp[cc];
            } else {
                #pragma unroll
                for (int cc = 0; cc < 7; cc++) v[cc] = 0ull;
            }
            #pragma unroll
            for (int r = 0; r < 2; r++) {
                int ky = dy - r;
                if (ky >= 0 && ky < 3) {
                    #pragma unroll
                    for (int o = 0; o < 2; o++)
                        #pragma unroll
                        for (int pw = 0; pw < 3; pw++)
                            #pragma unroll
                            for (int dx = 0; dx < 3; dx++)
                                fma2(acc[o][pw][r], v[2 * pw + dx], wd[o][ky * 3 + dx]);
                }
            }
        }
    }

    size_t obase = (img0 + ii) * 720;
    #pragma unroll
    for (int o = 0; o < 2; o++)
        #pragma unroll
        for (int pw = 0; pw < 3; pw++) {
            float v00, v01, v10, v11;
            unpack2(acc[o][pw][0], v00, v01);
            unpack2(acc[o][pw][1], v10, v11);
            float mx = fmaxf(fmaxf(v00, v01), fmaxf(v10, v11));
            g_feat2[obase + (2 * og + o) * 36 + ph * 6 + 3 * half + pw] = fmaxf(mx, 0.f);
        }
}

// ---------------------------------------------------------------------------
// conv3: (N,20,6,6) -> relu -> pool2 -> (N,40,3,3) -> g_x. 4 images / block.
// Pre-packed inputs (7 pairs/row) + pre-dup'd weights in dynamic SMEM.
// ---------------------------------------------------------------------------
__global__ void __launch_bounds__(256, 1)
k_conv3(const float* __restrict__ w3, const float* __restrict__ b3) {
    extern __shared__ __align__(16) ull dyn3[];
    ull* spk = dyn3;                 // 3360: [ii(4)][ic(20)][y(6)][cc(7)]
    ull* swd = dyn3 + 3360;          // 8000: [oc(40)][ic(20)] groups of 10
    __shared__ float sb[40];
    int tid = threadIdx.x;
    size_t img0 = (size_t)blockIdx.x * 4;

    for (int i = tid; i < 7200; i += 256) {
        int g = i / 9, q = i % 9;
        swd[g * 10 + q] = dup2(w3[i]);
    }
    for (int r = tid; r < 480; r += 256) {
        int ii = r / 120, rest = r % 120;
        int ic = rest / 6, y = rest % 6;
        const float2* sp = (const float2*)(g_feat2 + (img0 + ii) * 720 + ic * 36 + y * 6);
        float2 r0 = sp[0], r1 = sp[1], r2 = sp[2];
        ull* dst = spk + r * 7;      // r == (ii*20+ic)*6 + y
        dst[0] = pack2(0.f, r0.x);
        dst[1] = pack2(r0.x, r0.y);
        dst[2] = pack2(r0.y, r1.x);
        dst[3] = pack2(r1.x, r1.y);
        dst[4] = pack2(r1.y, r2.x);
        dst[5] = pack2(r2.x, r2.y);
        dst[6] = pack2(r2.y, 0.f);
    }
    if (tid < 40) sb[tid] = b3[tid];
    __syncthreads();

    if (tid >= 240) return;
    int ii  = tid / 60;
    int rem = tid % 60;
    int og  = rem / 3;
    int ph  = rem % 3;

    ull acc[2][3][2];
    #pragma unroll
    for (int o = 0; o < 2; o++) {
        ull bb = dup2(sb[2 * og + o]);
        #pragma unroll
        for (int pw = 0; pw < 3; pw++) { acc[o][pw][0] = bb; acc[o][pw][1] = bb; }
    }

    #pragma unroll 1
    for (int ic = 0; ic < 20; ic++) {
        ull wd[2][9];
        #pragma unroll
        for (int o = 0; o < 2; o++) {
            const ull* wp = swd + ((2 * og + o) * 20 + ic) * 10;
            const ulonglong2* wp2 = (const ulonglong2*)wp;
            ulonglong2 w01 = wp2[0], w23 = wp2[1], w45 = wp2[2], w67 = wp2[3];
            wd[o][0] = w01.x; wd[o][1] = w01.y; wd[o][2] = w23.x; wd[o][3] = w23.y;
            wd[o][4] = w45.x; wd[o][5] = w45.y; wd[o][6] = w67.x; wd[o][7] = w67.y;
            wd[o][8] = wp[8];
        }
        const ull* rb = spk + (ii * 20 + ic) * 42;   // 6 rows * 7
        #pragma unroll
        for (int dy = 0; dy < 4; dy++) {
            int y = 2 * ph - 1 + dy;
            ull v[7];
            if (y >= 0 && y < 6) {
                const ull* rp = rb + y * 7;
                #pragma unroll
                for (int cc = 0; cc < 7; cc++) v[cc] = rp[cc];
            } else {
                #pragma unroll
                for (int cc = 0; cc < 7; cc++) v[cc] = 0ull;
            }
            #pragma unroll
            for (int r = 0; r < 2; r++) {
                int ky = dy - r;
                if (ky >= 0 && ky < 3) {
                    #pragma unroll
                    for (int o = 0; o < 2; o++)
                        #pragma unroll
                        for (int pw = 0; pw < 3; pw++)
                            #pragma unroll
                            for (int dx = 0; dx < 3; dx++)
                                fma2(acc[o][pw][r], v[2 * pw + dx], wd[o][ky * 3 + dx]);
                }
            }
        }
    }

    size_t obase = (img0 + ii) * 360;
    #pragma unroll
    for (int o = 0; o < 2; o++)
        #pragma unroll
        for (int pw = 0; pw < 3; pw++) {
            float v00, v01, v10, v11;
            unpack2(acc[o][pw][0], v00, v01);
            unpack2(acc[o][pw][1], v10, v11);
            float mx = fmaxf(fmaxf(v00, v01), fmaxf(v10, v11));
            g_x[obase + (2 * og + o) * 9 + ph * 3 + pw] = fmaxf(mx, 0.f);
        }
}

// ---------------------------------------------------------------------------
// gates_x: stores interleaved g_gx[row*448 + jj*4 + gate].
// ---------------------------------------------------------------------------
__global__ void __launch_bounds__(448, 1)
k_gatesx(const float* __restrict__ w_ih,
         const float* __restrict__ b_ih, const float* __restrict__ b_hh) {
    __shared__ __align__(16) float sxp[36 * 32 * 2];
    int j = threadIdx.x;
    int jj = j % 112, g = j / 112;
    int outoff = jj * 4 + g;
    size_t row0 = (size_t)blockIdx.x * 64;
    const float* src = g_x + row0 * 36;
    for (int i = j; i < 2304; i += 448) {
        int row = i / 36, k = i % 36;
        sxp[(k * 32 + (row >> 1)) * 2 + (row & 1)] = src[i];
    }
    ull wd[36];
    {
        const float4* wp = (const float4*)(w_ih + j * 36);
        #pragma unroll
        for (int q = 0; q < 9; q++) {
            float4 v = wp[q];
            wd[4 * q] = dup2(v.x); wd[4 * q + 1] = dup2(v.y);
            wd[4 * q + 2] = dup2(v.z); wd[4 * q + 3] = dup2(v.w);
        }
    }
    float bias = b_ih[j] + b_hh[j];
    ull bias2 = dup2(bias);
    __syncthreads();

    const ull* sx2 = (const ull*)sxp;
    for (int rp = 0; rp < 32; rp++) {
        ull acc = bias2;
        #pragma unroll
        for (int k = 0; k < 36; k++)
            fma2(acc, sx2[k * 32 + rp], wd[k]);
        float lo, hi; unpack2(acc, lo, hi);
        g_gx[(row0 + 2 * rp) * G4 + outoff] = lo;
        g_gx[(row0 + 2 * rp + 1) * G4 + outoff] = hi;
    }
}

// ---------------------------------------------------------------------------
// Full LSTM recurrence in ONE kernel (R8 structure).
// ---------------------------------------------------------------------------
__global__ void __launch_bounds__(LSTM_THREADS, 1)
k_lstm(const float* __restrict__ h0, const float* __restrict__ c0,
       const float* __restrict__ wf, const float* __restrict__ bf,
       float* __restrict__ out) {
    extern __shared__ float sm[];
    float* ws = sm;
    float2* hs2 = (float2*)(sm + HID * G4);
    int tid = threadIdx.x;
    int j = tid % 112, ry = tid / 112;
    int mb = blockIdx.x * LROWS;

    {
        const float4* wsrc = (const float4*)g_whhT;
        float4* wdst = (float4*)ws;
        for (int i = tid; i < HID * G4 / 4; i += LSTM_THREADS) wdst[i] = wsrc[i];
    }
    float c[12];
    float h0j = h0[j], c0j = c0[j];
    #pragma unroll
    for (int p = 0; p < 6; p++) hs2[(ry * 6 + p) * 112 + j] = make_float2(h0j, h0j);
    #pragma unroll
    for (int i = 0; i < 12; i++) c[i] = c0j;

    int  rA[6];
    bool valid[6];
    #pragma unroll
    for (int p = 0; p < 6; p++) {
        rA[p] = mb + 2 * (ry * 6 + p);
        valid[p] = rA[p] < NB;
    }
    __syncthreads();

    for (int t = 0; t < T_STEPS; t++) {
        float4 gA[6], gB[6];
        size_t tb = (size_t)t * NB;
        #pragma unroll
        for (int p = 0; p < 6; p++) {
            int ra = valid[p] ? rA[p] : 0;
            int rb = valid[p] ? rA[p] + 1 : 0;
            gA[p] = ((const float4*)(g_gx + (tb + ra) * G4))[j];
            gB[p] = ((const float4*)(g_gx + (tb + rb) * G4))[j];
        }

        ull accp[6][4];
        #pragma unroll
        for (int p = 0; p < 6; p++)
            #pragma unroll
            for (int g = 0; g < 4; g++) accp[p][g] = 0ull;

        const ulonglong2* hv2 = (const ulonglong2*)hs2;
        #pragma unroll 2
        for (int kq = 0; kq < 56; kq++) {
            int k = kq * 2;
            ulonglong2 hv[6];
            #pragma unroll
            for (int p = 0; p < 6; p++)
                hv[p] = hv2[((ry * 6 + p) * 112 + k) >> 1];
            const float* wk = ws + k * G4 + j;
            ull wd0[4], wd1[4];
            #pragma unroll
            for (int g = 0; g < 4; g++) {
                wd0[g] = dup2(wk[g * 112]);
                wd1[g] = dup2(wk[G4 + g * 112]);
            }
            #pragma unroll
            for (int p = 0; p < 6; p++)
                #pragma unroll
                for (int g = 0; g < 4; g++) {
                    fma2(accp[p][g], hv[p].x, wd0[g]);
                    fma2(accp[p][g], hv[p].y, wd1[g]);
                }
        }
        __syncthreads();

        #pragma unroll
        for (int p = 0; p < 6; p++) {
            float a0[4], a1[4];
            #pragma unroll
            for (int g = 0; g < 4; g++) unpack2(accp[p][g], a0[g], a1[g]);

            float I0 = fsig(a0[0] + gA[p].x);
            float F0 = fsig(a0[1] + gA[p].y);
            float G0 = ftanh(a0[2] + gA[p].z);
            float O0 = fsig(a0[3] + gA[p].w);
            c[2 * p] = fmaf(F0, c[2 * p], I0 * G0);
            float hA = O0 * ftanh(c[2 * p]);

            float I1 = fsig(a1[0] + gB[p].x);
            float F1 = fsig(a1[1] + gB[p].y);
            float G1 = ftanh(a1[2] + gB[p].z);
            float O1 = fsig(a1[3] + gB[p].w);
            c[2 * p + 1] = fmaf(F1, c[2 * p + 1], I1 * G1);
            float hB = O1 * ftanh(c[2 * p + 1]);

            hs2[(ry * 6 + p) * 112 + j] = make_float2(hA, hB);
        }
        __syncthreads();
    }

    if (tid < LROWS && mb + tid < NB) {
        int pair = tid >> 1, comp = tid & 1;
        float l[3];
        #pragma unroll
        for (int o = 0; o < 3; o++) {
            float a = bf[o];
            const float* wo = wf + o * 112;
            #pragma unroll 4
            for (int k = 0; k < 112; k++) {
                float2 v = hs2[pair * 112 + k];
                a = fmaf(comp ? v.y : v.x, wo[k], a);
            }
            l[o] = a;
        }
        float m = fmaxf(l[0], fmaxf(l[1], l[2]));
        float e0 = expf(l[0] - m), e1 = expf(l[1] - m), e2 = expf(l[2] - m);
        float s = 1.f / (e0 + e1 + e2);
        float* op = out + (size_t)(mb + tid) * 3;
        op[0] = e0 * s; op[1] = e1 * s; op[2] = e2 * s;
    }
}

// ---------------------------------------------------------------------------
extern "C" void kernel_launch(void* const* d_in, const int* in_sizes, int n_in,
                              void* d_out, int out_size) {
    const float* imgs = (const float*)d_in[0];
    const float* w1   = (const float*)d_in[1];
    const float* b1   = (const float*)d_in[2];
    const float* w2   = (const float*)d_in[3];
    const float* b2   = (const float*)d_in[4];
    const float* w3   = (const float*)d_in[5];
    const float* b3   = (const float*)d_in[6];
    const float* w_ih = (const float*)d_in[7];
    const float* w_hh = (const float*)d_in[8];
    const float* b_ih = (const float*)d_in[9];
    const float* b_hh = (const float*)d_in[10];
    const float* wf   = (const float*)d_in[11];
    const float* bf   = (const float*)d_in[12];
    const float* h0   = (const float*)d_in[13];
    const float* c0   = (const float*)d_in[14];

    const int lstm_smem  = HID * G4 * 4 + 18 * 112 * 8;   // 216,832 B
    const int conv3_smem = (3360 + 8000) * 8;             // 90,880 B dynamic
    cudaFuncSetAttribute(k_lstm, cudaFuncAttributeMaxDynamicSharedMemorySize, lstm_smem);
    cudaFuncSetAttribute(k_conv3, cudaFuncAttributeMaxDynamicSharedMemorySize, conv3_smem);

    k_transpose<<<(HID * G4 + 255) / 256, 256>>>(w_hh);
    k_conv1<<<NIMG / 16, 256>>>(imgs, w1, b1);
    k_conv2<<<NIMG / 2, 256>>>(w2, b2);
    k_conv3<<<NIMG / 4, 256, conv3_smem>>>(w3, b3);
    k_gatesx<<<(T_STEPS * NB) / 64, 448>>>(w_ih, b_ih, b_hh);
    k_lstm<<<LSTM_BLOCKS, LSTM_THREADS, lstm_smem>>>(h0, c0, wf, bf, (float*)d_out);
}